// round 1
// baseline (speedup 1.0000x reference)
#include <cuda_runtime.h>
#include <cuda_bf16.h>
#include <cstdint>

#define N_USER 100000
#define N_GAME 50000
#define DDIM   256

// ---------------- scratch (device globals: no allocation allowed) ----------------
__device__ float g_agg_user[(size_t)N_USER * DDIM];   // sum of x_game[src] over rev edges
__device__ float g_agg_game[(size_t)N_GAME * DDIM];   // sum of x_user[src] over played edges
__device__ int   g_cnt_user[N_USER];
__device__ int   g_cnt_game[N_GAME];
__device__ float g_tmp[DDIM * DDIM];
__device__ float g_Wu[DDIM * DDIM];    // 0.125 * Wv_game @ Wm_rev @ Wout_user
__device__ float g_Wg[DDIM * DDIM];    // 0.125 * Wv_user @ Wm_played @ Wout_game
__device__ float g_v1u[DDIM];
__device__ float g_v1g[DDIM];
__device__ float g_eu[DDIM];           // 0.125*((bv_game@Wm_rev + bm_rev)@Wout_user)
__device__ float g_eg[DDIM];           // 0.125*((bv_user@Wm_played + bm_played)@Wout_game)

// ---------------- small 256x256x256 GEMM: C = scale * A @ B ----------------
__global__ void gemm256(const float* __restrict__ A, const float* __restrict__ B,
                        float* __restrict__ C, float scale)
{
    __shared__ float As[16][16];
    __shared__ float Bs[16][17];
    int tx = threadIdx.x, ty = threadIdx.y;
    int row = blockIdx.y * 16 + ty;
    int col = blockIdx.x * 16 + tx;
    float acc = 0.f;
    for (int kk = 0; kk < 256; kk += 16) {
        As[ty][tx] = A[row * 256 + kk + tx];
        Bs[ty][tx] = B[(kk + ty) * 256 + col];
        __syncthreads();
#pragma unroll
        for (int k = 0; k < 16; k++) acc += As[ty][k] * Bs[k][tx];
        __syncthreads();
    }
    C[row * 256 + col] = acc * scale;
}

// out[n] = scale * sum_j v[j]*M[j][n]  (+ badd[n] if badd != null)
__global__ void vecmat256(const float* __restrict__ v, const float* __restrict__ M,
                          const float* __restrict__ badd, float* __restrict__ outv,
                          float scale)
{
    int n = threadIdx.x;   // 256 threads
    float acc = 0.f;
#pragma unroll 8
    for (int j = 0; j < 256; j++) acc += v[j] * M[j * 256 + n];
    acc *= scale;
    if (badd) acc += badd[n];
    outv[n] = acc;
}

// ---------------- zeroing ----------------
__global__ void zero_f4(float4* p, int n4)
{
    int stride = gridDim.x * blockDim.x;
    for (int i = blockIdx.x * blockDim.x + threadIdx.x; i < n4; i += stride)
        p[i] = make_float4(0.f, 0.f, 0.f, 0.f);
}

// ---------------- edge scatter: one warp per edge ----------------
__device__ __forceinline__ void red_add_v4(float* p, float4 v)
{
#if defined(__CUDA_ARCH__) && (__CUDA_ARCH__ >= 900)
    asm volatile("red.global.add.v4.f32 [%0], {%1,%2,%3,%4};"
                 :: "l"(p), "f"(v.x), "f"(v.y), "f"(v.z), "f"(v.w) : "memory");
#else
    atomicAdd(p + 0, v.x); atomicAdd(p + 1, v.y);
    atomicAdd(p + 2, v.z); atomicAdd(p + 3, v.w);
#endif
}

__global__ void scatter_kernel(const float* __restrict__ X,
                               const int* __restrict__ src,
                               const int* __restrict__ dst, int E,
                               float* __restrict__ agg, int* __restrict__ cnt)
{
    int gw = (blockIdx.x * blockDim.x + threadIdx.x) >> 5;
    if (gw >= E) return;
    int lane = threadIdx.x & 31;
    int s = __ldg(src + gw);
    int d = __ldg(dst + gw);
    const float4* xs = (const float4*)(X + (size_t)s * DDIM);
    float*        ag = agg + (size_t)d * DDIM;
    float4 v0 = xs[lane];
    float4 v1 = xs[lane + 32];
    red_add_v4(ag + lane * 4, v0);
    red_add_v4(ag + 128 + lane * 4, v1);
    if (lane == 0) atomicAdd(cnt + d, 1);
}

// ---------------- fused finish GEMM ----------------
// Out[r] = relu( (Agg[r]/max(cnt[r],1)) @ W + bout + 1{cnt>0}*extra + X[r] )
#define BM 128
#define BN 64
#define BK 16

__global__ __launch_bounds__(256, 1)
void finish_gemm(const float* __restrict__ Agg, const int* __restrict__ cnt,
                 const float* __restrict__ X, const float* __restrict__ W,
                 const float* __restrict__ extra, const float* __restrict__ bout,
                 float* __restrict__ Out, int M)
{
    __shared__ float As[BK][BM];   // transposed A tile: As[k][m]
    __shared__ float Bs[BK][BN];   // Bs[k][n]

    const int tid = threadIdx.x;
    const int bm0 = blockIdx.x * BM;
    const int bn0 = blockIdx.y * BN;
    const int tn = tid & 15;       // 0..15 -> 4 columns each
    const int tm = tid >> 4;       // 0..15 -> 8 rows each

    float acc[8][4];
#pragma unroll
    for (int i = 0; i < 8; i++)
#pragma unroll
        for (int j = 0; j < 4; j++) acc[i][j] = 0.f;

    const int arow0 = tid >> 2;        // 0..63
    const int aq    = (tid & 3) * 4;   // 0,4,8,12
    const int brow  = tid >> 4;        // 0..15
    const int bcol  = (tid & 15) * 4;  // 0..60

    for (int kk = 0; kk < 256; kk += BK) {
        // A tile load (two rows per thread), store transposed
#pragma unroll
        for (int h = 0; h < 2; h++) {
            int r = arow0 + h * 64;
            int grow = bm0 + r;
            float4 v = make_float4(0.f, 0.f, 0.f, 0.f);
            if (grow < M)
                v = *(const float4*)(Agg + (size_t)grow * 256 + kk + aq);
            As[aq + 0][r] = v.x;
            As[aq + 1][r] = v.y;
            As[aq + 2][r] = v.z;
            As[aq + 3][r] = v.w;
        }
        // B tile load
        {
            float4 bv = *(const float4*)(W + (size_t)(kk + brow) * 256 + bn0 + bcol);
            *(float4*)&Bs[brow][bcol] = bv;
        }
        __syncthreads();

#pragma unroll
        for (int k = 0; k < BK; k++) {
            float4 a0 = *(const float4*)&As[k][tm * 8];
            float4 a1 = *(const float4*)&As[k][tm * 8 + 4];
            float4 b  = *(const float4*)&Bs[k][tn * 4];
            float a[8] = {a0.x, a0.y, a0.z, a0.w, a1.x, a1.y, a1.z, a1.w};
            float bb[4] = {b.x, b.y, b.z, b.w};
#pragma unroll
            for (int i = 0; i < 8; i++)
#pragma unroll
                for (int j = 0; j < 4; j++)
                    acc[i][j] += a[i] * bb[j];
        }
        __syncthreads();
    }

    // epilogue
    const int cbase = bn0 + tn * 4;
    const float4 ev = *(const float4*)(extra + cbase);
    const float4 bo = *(const float4*)(bout + cbase);
    const int rbase = bm0 + tm * 8;
#pragma unroll
    for (int i = 0; i < 8; i++) {
        int r = rbase + i;
        if (r < M) {
            int c = cnt[r];
            float inv = 1.0f / (float)(c > 1 ? c : 1);
            float on = (c > 0) ? 1.0f : 0.0f;
            float4 xv = *(const float4*)(X + (size_t)r * 256 + cbase);
            float4 o;
            o.x = fmaxf(acc[i][0] * inv + bo.x + on * ev.x + xv.x, 0.f);
            o.y = fmaxf(acc[i][1] * inv + bo.y + on * ev.y + xv.y, 0.f);
            o.z = fmaxf(acc[i][2] * inv + bo.z + on * ev.z + xv.z, 0.f);
            o.w = fmaxf(acc[i][3] * inv + bo.w + on * ev.w + xv.w, 0.f);
            *(float4*)(Out + (size_t)r * 256 + cbase) = o;
        }
    }
}

// ---------------- host launch ----------------
extern "C" void kernel_launch(void* const* d_in, const int* in_sizes, int n_in,
                              void* d_out, int out_size)
{
    const float* x_user    = (const float*)d_in[0];
    const float* x_game    = (const float*)d_in[1];
    // user: Wk(2) bk(3) Wq(4) bq(5) Wv(6) bv(7) Wout(8) bout(9)
    const float* Wv_user   = (const float*)d_in[6];
    const float* bv_user   = (const float*)d_in[7];
    const float* Wout_user = (const float*)d_in[8];
    const float* bout_user = (const float*)d_in[9];
    // game: Wk(10) bk(11) Wq(12) bq(13) Wv(14) bv(15) Wout(16) bout(17)
    const float* Wv_game   = (const float*)d_in[14];
    const float* bv_game   = (const float*)d_in[15];
    const float* Wout_game = (const float*)d_in[16];
    const float* bout_game = (const float*)d_in[17];
    // played: Wa(18) ba(19) Wm(20) bm(21) ; rev: Wa(22) ba(23) Wm(24) bm(25)
    const float* Wm_played = (const float*)d_in[20];
    const float* bm_played = (const float*)d_in[21];
    const float* Wm_rev    = (const float*)d_in[24];
    const float* bm_rev    = (const float*)d_in[25];
    const int* ps = (const int*)d_in[26];
    const int* pd = (const int*)d_in[27];
    const int* rs = (const int*)d_in[28];
    const int* rd = (const int*)d_in[29];
    const int E = in_sizes[26];

    float* out = (float*)d_out;

    float *agg_u, *agg_g, *tmp, *Wu, *Wg, *v1u, *v1g, *eu, *eg;
    int *cnt_u, *cnt_g;
    cudaGetSymbolAddress((void**)&agg_u, g_agg_user);
    cudaGetSymbolAddress((void**)&agg_g, g_agg_game);
    cudaGetSymbolAddress((void**)&cnt_u, g_cnt_user);
    cudaGetSymbolAddress((void**)&cnt_g, g_cnt_game);
    cudaGetSymbolAddress((void**)&tmp,   g_tmp);
    cudaGetSymbolAddress((void**)&Wu,    g_Wu);
    cudaGetSymbolAddress((void**)&Wg,    g_Wg);
    cudaGetSymbolAddress((void**)&v1u,   g_v1u);
    cudaGetSymbolAddress((void**)&v1g,   g_v1g);
    cudaGetSymbolAddress((void**)&eu,    g_eu);
    cudaGetSymbolAddress((void**)&eg,    g_eg);

    dim3 g16(16, 16), b16(16, 16);

    // fused weight chains (tiny)
    gemm256<<<g16, b16>>>(Wv_user, Wm_played, tmp, 1.0f);
    gemm256<<<g16, b16>>>(tmp, Wout_game, Wg, 0.125f);
    gemm256<<<g16, b16>>>(Wv_game, Wm_rev, tmp, 1.0f);
    gemm256<<<g16, b16>>>(tmp, Wout_user, Wu, 0.125f);

    vecmat256<<<1, 256>>>(bv_user, Wm_played, bm_played, v1g, 1.0f);
    vecmat256<<<1, 256>>>(v1g, Wout_game, nullptr, eg, 0.125f);
    vecmat256<<<1, 256>>>(bv_game, Wm_rev, bm_rev, v1u, 1.0f);
    vecmat256<<<1, 256>>>(v1u, Wout_user, nullptr, eu, 0.125f);

    // zero scratch
    zero_f4<<<4096, 256>>>((float4*)agg_u, N_USER * DDIM / 4);
    zero_f4<<<2048, 256>>>((float4*)agg_g, N_GAME * DDIM / 4);
    zero_f4<<<128, 256>>>((float4*)cnt_u, N_USER / 4);
    zero_f4<<<64, 256>>>((float4*)cnt_g, N_GAME / 4);

    // edge scatters (one warp per edge)
    int sblocks = (E * 32 + 255) / 256;
    scatter_kernel<<<sblocks, 256>>>(x_user, ps, pd, E, agg_g, cnt_g);
    scatter_kernel<<<sblocks, 256>>>(x_game, rs, rd, E, agg_u, cnt_u);

    // fused finish GEMMs
    finish_gemm<<<dim3((N_USER + BM - 1) / BM, 256 / BN), 256>>>(
        agg_u, cnt_u, x_user, Wu, eu, bout_user, out, N_USER);
    finish_gemm<<<dim3((N_GAME + BM - 1) / BM, 256 / BN), 256>>>(
        agg_g, cnt_g, x_game, Wg, eg, bout_game, out + (size_t)N_USER * DDIM, N_GAME);
}

// round 3
// speedup vs baseline: 1.8943x; 1.8943x over previous
#include <cuda_runtime.h>
#include <cuda_bf16.h>
#include <cstdint>

#define N_USER 100000
#define N_GAME 50000
#define DDIM   256

// ---------------- scratch (device globals) ----------------
__device__ float g_agg_user[(size_t)N_USER * DDIM];
__device__ float g_agg_game[(size_t)N_GAME * DDIM];
__device__ int   g_cnt_user[N_USER];
__device__ int   g_cnt_game[N_GAME];
__device__ float g_tmpA[DDIM * DDIM];
__device__ float g_tmpB[DDIM * DDIM];
__device__ __nv_bfloat16 g_Wub[DDIM * DDIM];  // bf16(0.125 * Wv_game @ Wm_rev @ Wout_user)
__device__ __nv_bfloat16 g_Wgb[DDIM * DDIM];  // bf16(0.125 * Wv_user @ Wm_played @ Wout_game)
__device__ float g_v1u[DDIM];
__device__ float g_v1g[DDIM];
__device__ float g_eu[DDIM];
__device__ float g_eg[DDIM];

// ---------------- batched tiny 256^3 GEMM (fp32 out) ----------------
__global__ void gemm256_pair(const float* __restrict__ A0, const float* __restrict__ B0,
                             float* __restrict__ C0,
                             const float* __restrict__ A1, const float* __restrict__ B1,
                             float* __restrict__ C1)
{
    const float* A = blockIdx.z ? A1 : A0;
    const float* B = blockIdx.z ? B1 : B0;
    float*       C = blockIdx.z ? C1 : C0;
    __shared__ float As[16][16];
    __shared__ float Bs[16][17];
    int tx = threadIdx.x, ty = threadIdx.y;
    int row = blockIdx.y * 16 + ty;
    int col = blockIdx.x * 16 + tx;
    float acc = 0.f;
    for (int kk = 0; kk < 256; kk += 16) {
        As[ty][tx] = A[row * 256 + kk + tx];
        Bs[ty][tx] = B[(kk + ty) * 256 + col];
        __syncthreads();
#pragma unroll
        for (int k = 0; k < 16; k++) acc += As[ty][k] * Bs[k][tx];
        __syncthreads();
    }
    C[row * 256 + col] = acc;
}

// batched tiny GEMM, scaled, bf16 output
__global__ void gemm256_pair_bf16(const float* __restrict__ A0, const float* __restrict__ B0,
                                  __nv_bfloat16* __restrict__ C0,
                                  const float* __restrict__ A1, const float* __restrict__ B1,
                                  __nv_bfloat16* __restrict__ C1, float scale)
{
    const float* A = blockIdx.z ? A1 : A0;
    const float* B = blockIdx.z ? B1 : B0;
    __nv_bfloat16* C = blockIdx.z ? C1 : C0;
    __shared__ float As[16][16];
    __shared__ float Bs[16][17];
    int tx = threadIdx.x, ty = threadIdx.y;
    int row = blockIdx.y * 16 + ty;
    int col = blockIdx.x * 16 + tx;
    float acc = 0.f;
    for (int kk = 0; kk < 256; kk += 16) {
        As[ty][tx] = A[row * 256 + kk + tx];
        Bs[ty][tx] = B[(kk + ty) * 256 + col];
        __syncthreads();
#pragma unroll
        for (int k = 0; k < 16; k++) acc += As[ty][k] * Bs[k][tx];
        __syncthreads();
    }
    C[row * 256 + col] = __float2bfloat16(acc * scale);
}

__global__ void vecmat256(const float* __restrict__ v, const float* __restrict__ M,
                          const float* __restrict__ badd, float* __restrict__ outv,
                          float scale)
{
    int n = threadIdx.x;
    float acc = 0.f;
#pragma unroll 8
    for (int j = 0; j < 256; j++) acc += v[j] * M[j * 256 + n];
    acc *= scale;
    if (badd) acc += badd[n];
    outv[n] = acc;
}

// ---------------- zeroing ----------------
__global__ void zero_f4(float4* p, int n4)
{
    int stride = gridDim.x * blockDim.x;
    for (int i = blockIdx.x * blockDim.x + threadIdx.x; i < n4; i += stride)
        p[i] = make_float4(0.f, 0.f, 0.f, 0.f);
}

// ---------------- edge scatter: one warp per edge ----------------
__device__ __forceinline__ void red_add_v4(float* p, float4 v)
{
    asm volatile("red.global.add.v4.f32 [%0], {%1,%2,%3,%4};"
                 :: "l"(p), "f"(v.x), "f"(v.y), "f"(v.z), "f"(v.w) : "memory");
}

__global__ void scatter_kernel(const float* __restrict__ X,
                               const int* __restrict__ src,
                               const int* __restrict__ dst, int E,
                               float* __restrict__ agg, int* __restrict__ cnt)
{
    int gw = (blockIdx.x * blockDim.x + threadIdx.x) >> 5;
    if (gw >= E) return;
    int lane = threadIdx.x & 31;
    int s = __ldg(src + gw);
    int d = __ldg(dst + gw);
    const float4* xs = (const float4*)(X + (size_t)s * DDIM);
    float*        ag = agg + (size_t)d * DDIM;
    float4 v0 = xs[lane];
    float4 v1 = xs[lane + 32];
    red_add_v4(ag + lane * 4, v0);
    red_add_v4(ag + 128 + lane * 4, v1);
    if (lane == 0) atomicAdd(cnt + d, 1);
}

// ---------------- tensor-core finish GEMM ----------------
// Out[r,:] = relu( bf16(Agg[r,:]/max(cnt,1)) @ Wb + bout + 1{cnt>0}*extra + X[r,:] )
// BM=128, BN=256 (full N), BK=16, 512 threads = 16 warps (4M x 4N), warp tile 32x64.

__device__ __forceinline__ uint32_t smem_u32(const void* p)
{
    return (uint32_t)__cvta_generic_to_shared(p);
}

__device__ __forceinline__ void ldsm_x4(uint32_t* r, uint32_t addr)
{
    asm volatile("ldmatrix.sync.aligned.m8n8.x4.shared.b16 {%0,%1,%2,%3}, [%4];"
                 : "=r"(r[0]), "=r"(r[1]), "=r"(r[2]), "=r"(r[3]) : "r"(addr));
}

__device__ __forceinline__ void ldsm_x4_t(uint32_t* r, uint32_t addr)
{
    asm volatile("ldmatrix.sync.aligned.m8n8.x4.trans.shared.b16 {%0,%1,%2,%3}, [%4];"
                 : "=r"(r[0]), "=r"(r[1]), "=r"(r[2]), "=r"(r[3]) : "r"(addr));
}

__device__ __forceinline__ void mma_bf16(float* c, const uint32_t* a, const uint32_t* b)
{
    asm volatile("mma.sync.aligned.m16n8k16.row.col.f32.bf16.bf16.f32 "
                 "{%0,%1,%2,%3}, {%4,%5,%6,%7}, {%8,%9}, {%0,%1,%2,%3};"
                 : "+f"(c[0]), "+f"(c[1]), "+f"(c[2]), "+f"(c[3])
                 : "r"(a[0]), "r"(a[1]), "r"(a[2]), "r"(a[3]), "r"(b[0]), "r"(b[1]));
}

#define FBM 128
#define FBN 256
#define FBK 16
// A smem row: 16 bf16 data padded to 24 bf16 (12 u32, 48B stride -> conflict-free ldmatrix)
// B smem row: 256 bf16 data padded to 264 (528B stride -> conflict-free ldmatrix.trans)

__global__ __launch_bounds__(512, 1)
void finish_mma(const float* __restrict__ Agg, const int* __restrict__ cnt,
                const float* __restrict__ X, const __nv_bfloat16* __restrict__ Wb,
                const float* __restrict__ extra, const float* __restrict__ bout,
                float* __restrict__ Out, int M)
{
    __shared__ uint32_t As[2][FBM][12];
    __shared__ __nv_bfloat16 Bs[2][FBK][264];
    __shared__ float invS[FBM];
    __shared__ float onS[FBM];

    const int tid = threadIdx.x;
    const int lane = tid & 31;
    const int warp = tid >> 5;
    const int wm0 = (warp >> 2) * 32;   // 0,32,64,96
    const int wn0 = (warp & 3) * 64;    // 0,64,128,192
    const int bm0 = blockIdx.x * FBM;

    // prologue: per-row scale + indicator
    if (tid < FBM) {
        int r = bm0 + tid;
        int c = (r < M) ? cnt[r] : 0;
        invS[tid] = 1.0f / (float)(c > 1 ? c : 1);
        onS[tid] = (c > 0) ? 1.0f : 0.0f;
    }
    __syncthreads();

    // A stage indices: 512 threads cover 128 rows x 4 quads of float4
    const int arow = tid >> 2;
    const int aq   = tid & 3;
    const int agrow = bm0 + arow;
    const float* aptr = Agg + (size_t)agrow * 256 + aq * 4;
    // B stage indices: 16 rows x 32 uint4
    const int brow = tid >> 5;
    const int bq   = tid & 31;
    const __nv_bfloat16* bptr = Wb + (size_t)brow * 256 + bq * 8;

    float4 aReg;
    uint4  bReg;

    // load tile 0
    {
        float inv = invS[arow];
        if (agrow < M) {
            aReg = *(const float4*)(aptr);
            aReg.x *= inv; aReg.y *= inv; aReg.z *= inv; aReg.w *= inv;
        } else aReg = make_float4(0.f, 0.f, 0.f, 0.f);
        bReg = *(const uint4*)(bptr);
        __nv_bfloat162 h0 = __floats2bfloat162_rn(aReg.x, aReg.y);
        __nv_bfloat162 h1 = __floats2bfloat162_rn(aReg.z, aReg.w);
        As[0][arow][aq * 2 + 0] = *(uint32_t*)&h0;
        As[0][arow][aq * 2 + 1] = *(uint32_t*)&h1;
        *(uint4*)&Bs[0][brow][bq * 8] = bReg;
    }
    __syncthreads();

    float acc[2][8][4];
#pragma unroll
    for (int mt = 0; mt < 2; mt++)
#pragma unroll
        for (int nt = 0; nt < 8; nt++)
#pragma unroll
            for (int j = 0; j < 4; j++) acc[mt][nt][j] = 0.f;

    const uint32_t asBase0 = smem_u32(&As[0][0][0]);
    const uint32_t asBase1 = smem_u32(&As[1][0][0]);
    const uint32_t bsBase0 = smem_u32(&Bs[0][0][0]);
    const uint32_t bsBase1 = smem_u32(&Bs[1][0][0]);

    for (int it = 0; it < 16; it++) {
        const int kk = (it + 1) * FBK;
        // prefetch next tile into regs
        if (it < 15) {
            float inv = invS[arow];
            if (agrow < M) {
                aReg = *(const float4*)(aptr + kk);
                aReg.x *= inv; aReg.y *= inv; aReg.z *= inv; aReg.w *= inv;
            } else aReg = make_float4(0.f, 0.f, 0.f, 0.f);
            bReg = *(const uint4*)(bptr + (size_t)kk * 256);
        }

        // compute from buffer it&1
        {
            const uint32_t aB = (it & 1) ? asBase1 : asBase0;
            const uint32_t bB = (it & 1) ? bsBase1 : bsBase0;
            uint32_t ra[2][4];
#pragma unroll
            for (int mt = 0; mt < 2; mt++) {
                uint32_t addr = aB + (uint32_t)(wm0 + mt * 16 + (lane & 15)) * 48u
                              + (uint32_t)(lane >> 4) * 16u;
                ldsm_x4(ra[mt], addr);
            }
#pragma unroll
            for (int p = 0; p < 4; p++) {
                uint32_t rb[4];
                uint32_t addr = bB + (uint32_t)(lane & 15) * 528u
                              + (uint32_t)(wn0 + p * 16 + ((lane >> 4) * 8)) * 2u;
                ldsm_x4_t(rb, addr);
#pragma unroll
                for (int mt = 0; mt < 2; mt++) {
                    mma_bf16(acc[mt][2 * p + 0], ra[mt], rb + 0);
                    mma_bf16(acc[mt][2 * p + 1], ra[mt], rb + 2);
                }
            }
        }

        // store prefetched regs into other buffer
        if (it < 15) {
            int nb = (it + 1) & 1;
            __nv_bfloat162 h0 = __floats2bfloat162_rn(aReg.x, aReg.y);
            __nv_bfloat162 h1 = __floats2bfloat162_rn(aReg.z, aReg.w);
            As[nb][arow][aq * 2 + 0] = *(uint32_t*)&h0;
            As[nb][arow][aq * 2 + 1] = *(uint32_t*)&h1;
            *(uint4*)&Bs[nb][brow][bq * 8] = bReg;
            __syncthreads();
        }
    }

    // epilogue
    const int groupID = lane >> 2;
    const int tig = lane & 3;
#pragma unroll
    for (int nt = 0; nt < 8; nt++) {
        const int col = wn0 + nt * 8 + tig * 2;
        const float2 bo = *(const float2*)(bout + col);
        const float2 ev = *(const float2*)(extra + col);
#pragma unroll
        for (int mt = 0; mt < 2; mt++) {
            const int lrow0 = wm0 + mt * 16 + groupID;
            const int row0 = bm0 + lrow0;
            if (row0 < M) {
                float on = onS[lrow0];
                float2 xv = *(const float2*)(X + (size_t)row0 * 256 + col);
                float2 o;
                o.x = fmaxf(acc[mt][nt][0] + bo.x + on * ev.x + xv.x, 0.f);
                o.y = fmaxf(acc[mt][nt][1] + bo.y + on * ev.y + xv.y, 0.f);
                *(float2*)(Out + (size_t)row0 * 256 + col) = o;
            }
            const int lrow1 = lrow0 + 8;
            const int row1 = row0 + 8;
            if (row1 < M) {
                float on = onS[lrow1];
                float2 xv = *(const float2*)(X + (size_t)row1 * 256 + col);
                float2 o;
                o.x = fmaxf(acc[mt][nt][2] + bo.x + on * ev.x + xv.x, 0.f);
                o.y = fmaxf(acc[mt][nt][3] + bo.y + on * ev.y + xv.y, 0.f);
                *(float2*)(Out + (size_t)row1 * 256 + col) = o;
            }
        }
    }
}

// ---------------- host launch ----------------
extern "C" void kernel_launch(void* const* d_in, const int* in_sizes, int n_in,
                              void* d_out, int out_size)
{
    const float* x_user    = (const float*)d_in[0];
    const float* x_game    = (const float*)d_in[1];
    const float* Wv_user   = (const float*)d_in[6];
    const float* bv_user   = (const float*)d_in[7];
    const float* Wout_user = (const float*)d_in[8];
    const float* bout_user = (const float*)d_in[9];
    const float* Wv_game   = (const float*)d_in[14];
    const float* bv_game   = (const float*)d_in[15];
    const float* Wout_game = (const float*)d_in[16];
    const float* bout_game = (const float*)d_in[17];
    const float* Wm_played = (const float*)d_in[20];
    const float* bm_played = (const float*)d_in[21];
    const float* Wm_rev    = (const float*)d_in[24];
    const float* bm_rev    = (const float*)d_in[25];
    const int* ps = (const int*)d_in[26];
    const int* pd = (const int*)d_in[27];
    const int* rs = (const int*)d_in[28];
    const int* rd = (const int*)d_in[29];
    const int E = in_sizes[26];

    float* out = (float*)d_out;

    float *agg_u, *agg_g, *tmpA, *tmpB, *v1u, *v1g, *eu, *eg;
    int *cnt_u, *cnt_g;
    __nv_bfloat16 *Wub, *Wgb;
    cudaGetSymbolAddress((void**)&agg_u, g_agg_user);
    cudaGetSymbolAddress((void**)&agg_g, g_agg_game);
    cudaGetSymbolAddress((void**)&cnt_u, g_cnt_user);
    cudaGetSymbolAddress((void**)&cnt_g, g_cnt_game);
    cudaGetSymbolAddress((void**)&tmpA,  g_tmpA);
    cudaGetSymbolAddress((void**)&tmpB,  g_tmpB);
    cudaGetSymbolAddress((void**)&Wub,   g_Wub);
    cudaGetSymbolAddress((void**)&Wgb,   g_Wgb);
    cudaGetSymbolAddress((void**)&v1u,   g_v1u);
    cudaGetSymbolAddress((void**)&v1g,   g_v1g);
    cudaGetSymbolAddress((void**)&eu,    g_eu);
    cudaGetSymbolAddress((void**)&eg,    g_eg);

    dim3 gz(16, 16, 2), b16(16, 16);

    // weight chains: tmpA = Wm_played@Wout_game ; tmpB = Wm_rev@Wout_user
    gemm256_pair<<<gz, b16>>>(Wm_played, Wout_game, tmpA, Wm_rev, Wout_user, tmpB);
    // Wgb = bf16(0.125*Wv_user@tmpA) ; Wub = bf16(0.125*Wv_game@tmpB)
    gemm256_pair_bf16<<<gz, b16>>>(Wv_user, tmpA, Wgb, Wv_game, tmpB, Wub, 0.125f);

    // bias chains (fp32, original weights)
    vecmat256<<<1, 256>>>(bv_user, Wm_played, bm_played, v1g, 1.0f);
    vecmat256<<<1, 256>>>(v1g, Wout_game, nullptr, eg, 0.125f);
    vecmat256<<<1, 256>>>(bv_game, Wm_rev, bm_rev, v1u, 1.0f);
    vecmat256<<<1, 256>>>(v1u, Wout_user, nullptr, eu, 0.125f);

    // zero scratch
    zero_f4<<<4096, 256>>>((float4*)agg_u, N_USER * DDIM / 4);
    zero_f4<<<2048, 256>>>((float4*)agg_g, N_GAME * DDIM / 4);
    zero_f4<<<128, 256>>>((float4*)cnt_u, N_USER / 4);
    zero_f4<<<64, 256>>>((float4*)cnt_g, N_GAME / 4);

    // edge scatters
    int sblocks = (E * 32 + 255) / 256;
    scatter_kernel<<<sblocks, 256>>>(x_user, ps, pd, E, agg_g, cnt_g);
    scatter_kernel<<<sblocks, 256>>>(x_game, rs, rd, E, agg_u, cnt_u);

    // tensor-core finish GEMMs
    finish_mma<<<(N_USER + FBM - 1) / FBM, 512>>>(
        agg_u, cnt_u, x_user, Wub, eu, bout_user, out, N_USER);
    finish_mma<<<(N_GAME + FBM - 1) / FBM, 512>>>(
        agg_g, cnt_g, x_game, Wgb, eg, bout_game, out + (size_t)N_USER * DDIM, N_GAME);
}

// round 6
// speedup vs baseline: 2.0022x; 1.0570x over previous
#include <cuda_runtime.h>
#include <cuda_bf16.h>
#include <cstdint>

#define N_USER 100000
#define N_GAME 50000
#define DDIM   256

// ---------------- scratch (device globals) ----------------
__device__ float g_agg_user[(size_t)N_USER * DDIM];
__device__ float g_agg_game[(size_t)N_GAME * DDIM];
__device__ int   g_cnt_user[N_USER];
__device__ int   g_cnt_game[N_GAME];
__device__ float g_tmpA[DDIM * DDIM];   // Wm_played @ Wout_game
__device__ float g_tmpB[DDIM * DDIM];   // Wm_rev @ Wout_user
__device__ __nv_bfloat16 g_Wub[DDIM * DDIM];  // bf16(0.125 * Wv_game @ tmpB)
__device__ __nv_bfloat16 g_Wgb[DDIM * DDIM];  // bf16(0.125 * Wv_user @ tmpA)
__device__ float g_eu[DDIM];
__device__ float g_eg[DDIM];

// ---------------- batched tiny 256^3 GEMM (fp32 out) ----------------
__global__ void gemm256_pair(const float* __restrict__ A0, const float* __restrict__ B0,
                             float* __restrict__ C0,
                             const float* __restrict__ A1, const float* __restrict__ B1,
                             float* __restrict__ C1)
{
    const float* A = blockIdx.z ? A1 : A0;
    const float* B = blockIdx.z ? B1 : B0;
    float*       C = blockIdx.z ? C1 : C0;
    __shared__ float As[16][16];
    __shared__ float Bs[16][17];
    int tx = threadIdx.x, ty = threadIdx.y;
    int row = blockIdx.y * 16 + ty;
    int col = blockIdx.x * 16 + tx;
    float acc = 0.f;
    for (int kk = 0; kk < 256; kk += 16) {
        As[ty][tx] = A[row * 256 + kk + tx];
        Bs[ty][tx] = B[(kk + ty) * 256 + col];
        __syncthreads();
#pragma unroll
        for (int k = 0; k < 16; k++) acc += As[ty][k] * Bs[k][tx];
        __syncthreads();
    }
    C[row * 256 + col] = acc;
}

// batched tiny GEMM, scaled, bf16 output
__global__ void gemm256_pair_bf16(const float* __restrict__ A0, const float* __restrict__ B0,
                                  __nv_bfloat16* __restrict__ C0,
                                  const float* __restrict__ A1, const float* __restrict__ B1,
                                  __nv_bfloat16* __restrict__ C1, float scale)
{
    const float* A = blockIdx.z ? A1 : A0;
    const float* B = blockIdx.z ? B1 : B0;
    __nv_bfloat16* C = blockIdx.z ? C1 : C0;
    __shared__ float As[16][16];
    __shared__ float Bs[16][17];
    int tx = threadIdx.x, ty = threadIdx.y;
    int row = blockIdx.y * 16 + ty;
    int col = blockIdx.x * 16 + tx;
    float acc = 0.f;
    for (int kk = 0; kk < 256; kk += 16) {
        As[ty][tx] = A[row * 256 + kk + tx];
        Bs[ty][tx] = B[(kk + ty) * 256 + col];
        __syncthreads();
#pragma unroll
        for (int k = 0; k < 16; k++) acc += As[ty][k] * Bs[k][tx];
        __syncthreads();
    }
    C[row * 256 + col] = __float2bfloat16(acc * scale);
}

// ---------------- fused bias chains (one parallel launch, no serial chain) ----
// e[n] = 0.125 * ( sum_j bv[j]*T[j][n] + sum_j bm[j]*W[j][n] )
__global__ void vecmat_combo(const float* __restrict__ bv0, const float* __restrict__ T0,
                             const float* __restrict__ bm0, const float* __restrict__ W0,
                             float* __restrict__ e0,
                             const float* __restrict__ bv1, const float* __restrict__ T1,
                             const float* __restrict__ bm1, const float* __restrict__ W1,
                             float* __restrict__ e1)
{
    const float* bv = blockIdx.x ? bv1 : bv0;
    const float* T  = blockIdx.x ? T1  : T0;
    const float* bm = blockIdx.x ? bm1 : bm0;
    const float* W  = blockIdx.x ? W1  : W0;
    float*       e  = blockIdx.x ? e1  : e0;
    int n = threadIdx.x;
    float acc = 0.f;
#pragma unroll 8
    for (int j = 0; j < 256; j++)
        acc += bv[j] * T[j * 256 + n] + bm[j] * W[j * 256 + n];
    e[n] = 0.125f * acc;
}

// ---------------- edge scatter: one warp per edge ----------------
__device__ __forceinline__ void red_add_v4(float* p, float4 v)
{
    asm volatile("red.global.add.v4.f32 [%0], {%1,%2,%3,%4};"
                 :: "l"(p), "f"(v.x), "f"(v.y), "f"(v.z), "f"(v.w) : "memory");
}

__global__ void scatter_kernel(const float* __restrict__ X,
                               const int* __restrict__ src,
                               const int* __restrict__ dst, int E,
                               float* __restrict__ agg, int* __restrict__ cnt)
{
    int gw = (blockIdx.x * blockDim.x + threadIdx.x) >> 5;
    if (gw >= E) return;
    int lane = threadIdx.x & 31;
    int s = __ldg(src + gw);
    int d = __ldg(dst + gw);
    const float4* xs = (const float4*)(X + (size_t)s * DDIM);
    float*        ag = agg + (size_t)d * DDIM;
    float4 v0 = xs[lane];
    float4 v1 = xs[lane + 32];
    red_add_v4(ag + lane * 4, v0);
    red_add_v4(ag + 128 + lane * 4, v1);
    if (lane == 0) atomicAdd(cnt + d, 1);
}

// ---------------- tensor-core finish GEMM ----------------
// Out[r,:] = relu( bf16(Agg[r,:]/max(cnt,1)) @ Wb + bout + 1{cnt>0}*extra + X[r,:] )
// BM=128, BN=256 (full N), BK=16, 512 threads = 16 warps (4M x 4N), warp tile 32x64.

__device__ __forceinline__ uint32_t smem_u32(const void* p)
{
    return (uint32_t)__cvta_generic_to_shared(p);
}

__device__ __forceinline__ void ldsm_x4(uint32_t* r, uint32_t addr)
{
    asm volatile("ldmatrix.sync.aligned.m8n8.x4.shared.b16 {%0,%1,%2,%3}, [%4];"
                 : "=r"(r[0]), "=r"(r[1]), "=r"(r[2]), "=r"(r[3]) : "r"(addr));
}

__device__ __forceinline__ void ldsm_x4_t(uint32_t* r, uint32_t addr)
{
    asm volatile("ldmatrix.sync.aligned.m8n8.x4.trans.shared.b16 {%0,%1,%2,%3}, [%4];"
                 : "=r"(r[0]), "=r"(r[1]), "=r"(r[2]), "=r"(r[3]) : "r"(addr));
}

__device__ __forceinline__ void mma_bf16(float* c, const uint32_t* a, const uint32_t* b)
{
    asm volatile("mma.sync.aligned.m16n8k16.row.col.f32.bf16.bf16.f32 "
                 "{%0,%1,%2,%3}, {%4,%5,%6,%7}, {%8,%9}, {%0,%1,%2,%3};"
                 : "+f"(c[0]), "+f"(c[1]), "+f"(c[2]), "+f"(c[3])
                 : "r"(a[0]), "r"(a[1]), "r"(a[2]), "r"(a[3]), "r"(b[0]), "r"(b[1]));
}

#define FBM 128
#define FBN 256
#define FBK 16

__global__ __launch_bounds__(512, 1)
void finish_mma(const float* __restrict__ Agg, const int* __restrict__ cnt,
                const float* __restrict__ X, const __nv_bfloat16* __restrict__ Wb,
                const float* __restrict__ extra, const float* __restrict__ bout,
                float* __restrict__ Out, int M)
{
    __shared__ uint32_t As[2][FBM][12];
    __shared__ __nv_bfloat16 Bs[2][FBK][264];
    __shared__ float invS[FBM];
    __shared__ float onS[FBM];

    const int tid = threadIdx.x;
    const int lane = tid & 31;
    const int warp = tid >> 5;
    const int wm0 = (warp >> 2) * 32;   // 0,32,64,96
    const int wn0 = (warp & 3) * 64;    // 0,64,128,192
    const int bm0 = blockIdx.x * FBM;

    if (tid < FBM) {
        int r = bm0 + tid;
        int c = (r < M) ? cnt[r] : 0;
        invS[tid] = 1.0f / (float)(c > 1 ? c : 1);
        onS[tid] = (c > 0) ? 1.0f : 0.0f;
    }
    __syncthreads();

    const int arow = tid >> 2;
    const int aq   = tid & 3;
    const int agrow = bm0 + arow;
    const float* aptr = Agg + (size_t)agrow * 256 + aq * 4;
    const int brow = tid >> 5;
    const int bq   = tid & 31;
    const __nv_bfloat16* bptr = Wb + (size_t)brow * 256 + bq * 8;

    float4 aReg;
    uint4  bReg;

    {
        float inv = invS[arow];
        if (agrow < M) {
            aReg = *(const float4*)(aptr);
            aReg.x *= inv; aReg.y *= inv; aReg.z *= inv; aReg.w *= inv;
        } else aReg = make_float4(0.f, 0.f, 0.f, 0.f);
        bReg = *(const uint4*)(bptr);
        __nv_bfloat162 h0 = __floats2bfloat162_rn(aReg.x, aReg.y);
        __nv_bfloat162 h1 = __floats2bfloat162_rn(aReg.z, aReg.w);
        As[0][arow][aq * 2 + 0] = *(uint32_t*)&h0;
        As[0][arow][aq * 2 + 1] = *(uint32_t*)&h1;
        *(uint4*)&Bs[0][brow][bq * 8] = bReg;
    }
    __syncthreads();

    float acc[2][8][4];
#pragma unroll
    for (int mt = 0; mt < 2; mt++)
#pragma unroll
        for (int nt = 0; nt < 8; nt++)
#pragma unroll
            for (int j = 0; j < 4; j++) acc[mt][nt][j] = 0.f;

    const uint32_t asBase0 = smem_u32(&As[0][0][0]);
    const uint32_t asBase1 = smem_u32(&As[1][0][0]);
    const uint32_t bsBase0 = smem_u32(&Bs[0][0][0]);
    const uint32_t bsBase1 = smem_u32(&Bs[1][0][0]);

    for (int it = 0; it < 16; it++) {
        const int kk = (it + 1) * FBK;
        if (it < 15) {
            float inv = invS[arow];
            if (agrow < M) {
                aReg = *(const float4*)(aptr + kk);
                aReg.x *= inv; aReg.y *= inv; aReg.z *= inv; aReg.w *= inv;
            } else aReg = make_float4(0.f, 0.f, 0.f, 0.f);
            bReg = *(const uint4*)(bptr + (size_t)kk * 256);
        }

        {
            const uint32_t aB = (it & 1) ? asBase1 : asBase0;
            const uint32_t bB = (it & 1) ? bsBase1 : bsBase0;
            uint32_t ra[2][4];
#pragma unroll
            for (int mt = 0; mt < 2; mt++) {
                uint32_t addr = aB + (uint32_t)(wm0 + mt * 16 + (lane & 15)) * 48u
                              + (uint32_t)(lane >> 4) * 16u;
                ldsm_x4(ra[mt], addr);
            }
#pragma unroll
            for (int p = 0; p < 4; p++) {
                uint32_t rb[4];
                uint32_t addr = bB + (uint32_t)(lane & 15) * 528u
                              + (uint32_t)(wn0 + p * 16 + ((lane >> 4) * 8)) * 2u;
                ldsm_x4_t(rb, addr);
#pragma unroll
                for (int mt = 0; mt < 2; mt++) {
                    mma_bf16(acc[mt][2 * p + 0], ra[mt], rb + 0);
                    mma_bf16(acc[mt][2 * p + 1], ra[mt], rb + 2);
                }
            }
        }

        if (it < 15) {
            int nb = (it + 1) & 1;
            __nv_bfloat162 h0 = __floats2bfloat162_rn(aReg.x, aReg.y);
            __nv_bfloat162 h1 = __floats2bfloat162_rn(aReg.z, aReg.w);
            As[nb][arow][aq * 2 + 0] = *(uint32_t*)&h0;
            As[nb][arow][aq * 2 + 1] = *(uint32_t*)&h1;
            *(uint4*)&Bs[nb][brow][bq * 8] = bReg;
            __syncthreads();
        }
    }

    const int groupID = lane >> 2;
    const int tig = lane & 3;
#pragma unroll
    for (int nt = 0; nt < 8; nt++) {
        const int col = wn0 + nt * 8 + tig * 2;
        const float2 bo = *(const float2*)(bout + col);
        const float2 ev = *(const float2*)(extra + col);
#pragma unroll
        for (int mt = 0; mt < 2; mt++) {
            const int lrow0 = wm0 + mt * 16 + groupID;
            const int row0 = bm0 + lrow0;
            if (row0 < M) {
                float on = onS[lrow0];
                float2 xv = *(const float2*)(X + (size_t)row0 * 256 + col);
                float2 o;
                o.x = fmaxf(acc[mt][nt][0] + bo.x + on * ev.x + xv.x, 0.f);
                o.y = fmaxf(acc[mt][nt][1] + bo.y + on * ev.y + xv.y, 0.f);
                *(float2*)(Out + (size_t)row0 * 256 + col) = o;
            }
            const int lrow1 = lrow0 + 8;
            const int row1 = row0 + 8;
            if (row1 < M) {
                float on = onS[lrow1];
                float2 xv = *(const float2*)(X + (size_t)row1 * 256 + col);
                float2 o;
                o.x = fmaxf(acc[mt][nt][2] + bo.x + on * ev.x + xv.x, 0.f);
                o.y = fmaxf(acc[mt][nt][3] + bo.y + on * ev.y + xv.y, 0.f);
                *(float2*)(Out + (size_t)row1 * 256 + col) = o;
            }
        }
    }
}

// ---------------- host launch ----------------
extern "C" void kernel_launch(void* const* d_in, const int* in_sizes, int n_in,
                              void* d_out, int out_size)
{
    const float* x_user    = (const float*)d_in[0];
    const float* x_game    = (const float*)d_in[1];
    const float* Wv_user   = (const float*)d_in[6];
    const float* bv_user   = (const float*)d_in[7];
    const float* Wout_user = (const float*)d_in[8];
    const float* bout_user = (const float*)d_in[9];
    const float* Wv_game   = (const float*)d_in[14];
    const float* bv_game   = (const float*)d_in[15];
    const float* Wout_game = (const float*)d_in[16];
    const float* bout_game = (const float*)d_in[17];
    const float* Wm_played = (const float*)d_in[20];
    const float* bm_played = (const float*)d_in[21];
    const float* Wm_rev    = (const float*)d_in[24];
    const float* bm_rev    = (const float*)d_in[25];
    const int* ps = (const int*)d_in[26];
    const int* pd = (const int*)d_in[27];
    const int* rs = (const int*)d_in[28];
    const int* rd = (const int*)d_in[29];
    const int E = in_sizes[26];

    float* out = (float*)d_out;

    float *agg_u, *agg_g, *tmpA, *tmpB, *eu, *eg;
    int *cnt_u, *cnt_g;
    __nv_bfloat16 *Wub, *Wgb;
    cudaGetSymbolAddress((void**)&agg_u, g_agg_user);
    cudaGetSymbolAddress((void**)&agg_g, g_agg_game);
    cudaGetSymbolAddress((void**)&cnt_u, g_cnt_user);
    cudaGetSymbolAddress((void**)&cnt_g, g_cnt_game);
    cudaGetSymbolAddress((void**)&tmpA,  g_tmpA);
    cudaGetSymbolAddress((void**)&tmpB,  g_tmpB);
    cudaGetSymbolAddress((void**)&Wub,   g_Wub);
    cudaGetSymbolAddress((void**)&Wgb,   g_Wgb);
    cudaGetSymbolAddress((void**)&eu,    g_eu);
    cudaGetSymbolAddress((void**)&eg,    g_eg);

    // zero scratch via memset nodes (not kernel launches -> keeps ncu index on real kernels)
    cudaMemsetAsync(agg_u, 0, (size_t)N_USER * DDIM * sizeof(float));
    cudaMemsetAsync(agg_g, 0, (size_t)N_GAME * DDIM * sizeof(float));
    cudaMemsetAsync(cnt_u, 0, (size_t)N_USER * sizeof(int));
    cudaMemsetAsync(cnt_g, 0, (size_t)N_GAME * sizeof(int));

    dim3 gz(16, 16, 2), b16(16, 16);

    // kernel 0: tmpA = Wm_played@Wout_game ; tmpB = Wm_rev@Wout_user
    gemm256_pair<<<gz, b16>>>(Wm_played, Wout_game, tmpA, Wm_rev, Wout_user, tmpB);
    // kernel 1: Wgb = bf16(0.125*Wv_user@tmpA) ; Wub = bf16(0.125*Wv_game@tmpB)
    gemm256_pair_bf16<<<gz, b16>>>(Wv_user, tmpA, Wgb, Wv_game, tmpB, Wub, 0.125f);
    // kernel 2: fused bias chains
    // eg = 0.125*(bv_user@tmpA + bm_played@Wout_game)
    // eu = 0.125*(bv_game@tmpB + bm_rev@Wout_user)
    vecmat_combo<<<2, 256>>>(bv_user, tmpA, bm_played, Wout_game, eg,
                             bv_game, tmpB, bm_rev, Wout_user, eu);

    // kernels 3,4: edge scatters
    int sblocks = (E * 32 + 255) / 256;
    scatter_kernel<<<sblocks, 256>>>(x_user, ps, pd, E, agg_g, cnt_g);
    scatter_kernel<<<sblocks, 256>>>(x_game, rs, rd, E, agg_u, cnt_u);

    // kernel 5 (profiled by ncu -s 5): big finish GEMM (user)
    finish_mma<<<(N_USER + FBM - 1) / FBM, 512>>>(
        agg_u, cnt_u, x_user, Wub, eu, bout_user, out, N_USER);
    // kernel 6: finish GEMM (game)
    finish_mma<<<(N_GAME + FBM - 1) / FBM, 512>>>(
        agg_g, cnt_g, x_game, Wgb, eg, bout_game, out + (size_t)N_USER * DDIM, N_GAME);
}

// round 8
// speedup vs baseline: 2.5399x; 1.2685x over previous
#include <cuda_runtime.h>
#include <cuda_bf16.h>
#include <cstdint>

#define N_USER 100000
#define N_GAME 50000
#define DDIM   256
#define EMAX   200000

// ---------------- scratch (device globals) ----------------
__device__ int   g_rp_u[N_USER + 1];    // CSR rowptr (user dst, rev edges)
__device__ int   g_rp_g[N_GAME + 1];    // CSR rowptr (game dst, played edges)
__device__ int   g_cur_u[N_USER];
__device__ int   g_cur_g[N_GAME];
__device__ int   g_srcs_u[EMAX];        // game-node sources sorted by user dst
__device__ int   g_srcs_g[EMAX];        // user-node sources sorted by game dst
__device__ int   g_part_u[128];
__device__ int   g_part_g[128];
__device__ float g_tmpA[DDIM * DDIM];   // Wm_played @ Wout_game
__device__ float g_tmpB[DDIM * DDIM];   // Wm_rev @ Wout_user
__device__ __nv_bfloat16 g_Wub[DDIM * DDIM];  // bf16(0.125 * Wv_game @ tmpB)
__device__ __nv_bfloat16 g_Wgb[DDIM * DDIM];  // bf16(0.125 * Wv_user @ tmpA)
__device__ float g_eu[DDIM];
__device__ float g_eg[DDIM];

// ---------------- batched tiny 256^3 GEMM (fp32 out) ----------------
__global__ void gemm256_pair(const float* __restrict__ A0, const float* __restrict__ B0,
                             float* __restrict__ C0,
                             const float* __restrict__ A1, const float* __restrict__ B1,
                             float* __restrict__ C1)
{
    const float* A = blockIdx.z ? A1 : A0;
    const float* B = blockIdx.z ? B1 : B0;
    float*       C = blockIdx.z ? C1 : C0;
    __shared__ float As[16][16];
    __shared__ float Bs[16][17];
    int tx = threadIdx.x, ty = threadIdx.y;
    int row = blockIdx.y * 16 + ty;
    int col = blockIdx.x * 16 + tx;
    float acc = 0.f;
    for (int kk = 0; kk < 256; kk += 16) {
        As[ty][tx] = A[row * 256 + kk + tx];
        Bs[ty][tx] = B[(kk + ty) * 256 + col];
        __syncthreads();
#pragma unroll
        for (int k = 0; k < 16; k++) acc += As[ty][k] * Bs[k][tx];
        __syncthreads();
    }
    C[row * 256 + col] = acc;
}

__global__ void gemm256_pair_bf16(const float* __restrict__ A0, const float* __restrict__ B0,
                                  __nv_bfloat16* __restrict__ C0,
                                  const float* __restrict__ A1, const float* __restrict__ B1,
                                  __nv_bfloat16* __restrict__ C1, float scale)
{
    const float* A = blockIdx.z ? A1 : A0;
    const float* B = blockIdx.z ? B1 : B0;
    __nv_bfloat16* C = blockIdx.z ? C1 : C0;
    __shared__ float As[16][16];
    __shared__ float Bs[16][17];
    int tx = threadIdx.x, ty = threadIdx.y;
    int row = blockIdx.y * 16 + ty;
    int col = blockIdx.x * 16 + tx;
    float acc = 0.f;
    for (int kk = 0; kk < 256; kk += 16) {
        As[ty][tx] = A[row * 256 + kk + tx];
        Bs[ty][tx] = B[(kk + ty) * 256 + col];
        __syncthreads();
#pragma unroll
        for (int k = 0; k < 16; k++) acc += As[ty][k] * Bs[k][tx];
        __syncthreads();
    }
    C[row * 256 + col] = __float2bfloat16(acc * scale);
}

// ---------------- fused bias chains ----------------
__global__ void vecmat_combo(const float* __restrict__ bv0, const float* __restrict__ T0,
                             const float* __restrict__ bm0, const float* __restrict__ W0,
                             float* __restrict__ e0,
                             const float* __restrict__ bv1, const float* __restrict__ T1,
                             const float* __restrict__ bm1, const float* __restrict__ W1,
                             float* __restrict__ e1)
{
    const float* bv = blockIdx.x ? bv1 : bv0;
    const float* T  = blockIdx.x ? T1  : T0;
    const float* bm = blockIdx.x ? bm1 : bm0;
    const float* W  = blockIdx.x ? W1  : W0;
    float*       e  = blockIdx.x ? e1  : e0;
    int n = threadIdx.x;
    float acc = 0.f;
#pragma unroll 8
    for (int j = 0; j < 256; j++)
        acc += bv[j] * T[j * 256 + n] + bm[j] * W[j * 256 + n];
    e[n] = 0.125f * acc;
}

// ---------------- CSR build ----------------
__global__ void hist2(const int* __restrict__ pd, const int* __restrict__ rd, int E,
                      int* __restrict__ rp_g, int* __restrict__ rp_u)
{
    int i = blockIdx.x * blockDim.x + threadIdx.x;
    if (i < E) {
        atomicAdd(&rp_g[pd[i] + 1], 1);
        atomicAdd(&rp_u[rd[i] + 1], 1);
    }
}

// per-block partial sums over 1024-chunks (y selects user/game)
__global__ void scanA(const int* __restrict__ in_u, int len_u, int* __restrict__ part_u,
                      const int* __restrict__ in_g, int len_g, int* __restrict__ part_g)
{
    const int* in  = blockIdx.y ? in_g  : in_u;
    const int len  = blockIdx.y ? len_g : len_u;
    int* part      = blockIdx.y ? part_g : part_u;
    int t = threadIdx.x;
    int idx = blockIdx.x * 1024 + t;
    int v = (idx < len) ? in[idx] : 0;
    int lane = t & 31, wid = t >> 5;
#pragma unroll
    for (int o = 16; o; o >>= 1) v += __shfl_down_sync(0xFFFFFFFFu, v, o);
    __shared__ int ws[32];
    if (lane == 0) ws[wid] = v;
    __syncthreads();
    if (wid == 0) {
        int s = ws[lane];
#pragma unroll
        for (int o = 16; o; o >>= 1) s += __shfl_down_sync(0xFFFFFFFFu, s, o);
        if (lane == 0) part[blockIdx.x] = s;
    }
}

// in-place inclusive scan with block offset from partials; also init cursor=rowptr
__global__ void scanC(int* __restrict__ rp_u, int len_u, const int* __restrict__ part_u,
                      int* __restrict__ cur_u,
                      int* __restrict__ rp_g, int len_g, const int* __restrict__ part_g,
                      int* __restrict__ cur_g)
{
    int* rp        = blockIdx.y ? rp_g  : rp_u;
    const int len  = blockIdx.y ? len_g : len_u;
    const int* part = blockIdx.y ? part_g : part_u;
    int* cur       = blockIdx.y ? cur_g : cur_u;

    __shared__ int sp[128];
    int t = threadIdx.x;
    if (t < 128) sp[t] = (t < (int)gridDim.x) ? part[t] : 0;
    __syncthreads();
    int offset = 0;
    for (int j = 0; j < (int)blockIdx.x; j++) offset += sp[j];

    int idx = blockIdx.x * 1024 + t;
    int x = (idx < len) ? rp[idx] : 0;
    int lane = t & 31, wid = t >> 5;
#pragma unroll
    for (int o = 1; o < 32; o <<= 1) {
        int n = __shfl_up_sync(0xFFFFFFFFu, x, o);
        if (lane >= o) x += n;
    }
    __shared__ int wsum[32];
    if (lane == 31) wsum[wid] = x;
    __syncthreads();
    if (wid == 0) {
        int y = wsum[lane];
#pragma unroll
        for (int o = 1; o < 32; o <<= 1) {
            int n = __shfl_up_sync(0xFFFFFFFFu, y, o);
            if (lane >= o) y += n;
        }
        wsum[lane] = y;
    }
    __syncthreads();
    int incl = x + (wid > 0 ? wsum[wid - 1] : 0) + offset;
    if (idx < len) {
        rp[idx] = incl;
        if (idx < len - 1) cur[idx] = incl;
    }
}

__global__ void bin_kernel(const int* __restrict__ ps, const int* __restrict__ pd,
                           const int* __restrict__ rs, const int* __restrict__ rd, int E,
                           int* __restrict__ cur_g, int* __restrict__ srcs_g,
                           int* __restrict__ cur_u, int* __restrict__ srcs_u)
{
    int i = blockIdx.x * blockDim.x + threadIdx.x;
    if (i < E) {
        int dg = pd[i];
        int p = atomicAdd(&cur_g[dg], 1);
        srcs_g[p] = ps[i];
        int du = rd[i];
        int q = atomicAdd(&cur_u[du], 1);
        srcs_u[q] = rs[i];
    }
}

// ---------------- fused gather + tensor-core GEMM ----------------
// Per 128-row dst tile:
//  phase1: warp-per-row gather of src feature rows, mean-normalize, bf16 -> smem A
//  phase2: MMA over resident A, B double-buffered from global (L2-resident)
//  epilogue: + bout + 1{deg>0}*extra + Xres, ReLU
__device__ __forceinline__ uint32_t smem_u32(const void* p)
{
    return (uint32_t)__cvta_generic_to_shared(p);
}

__device__ __forceinline__ void ldsm_x4(uint32_t* r, uint32_t addr)
{
    asm volatile("ldmatrix.sync.aligned.m8n8.x4.shared.b16 {%0,%1,%2,%3}, [%4];"
                 : "=r"(r[0]), "=r"(r[1]), "=r"(r[2]), "=r"(r[3]) : "r"(addr));
}

__device__ __forceinline__ void ldsm_x4_t(uint32_t* r, uint32_t addr)
{
    asm volatile("ldmatrix.sync.aligned.m8n8.x4.trans.shared.b16 {%0,%1,%2,%3}, [%4];"
                 : "=r"(r[0]), "=r"(r[1]), "=r"(r[2]), "=r"(r[3]) : "r"(addr));
}

__device__ __forceinline__ void mma_bf16(float* c, const uint32_t* a, const uint32_t* b)
{
    asm volatile("mma.sync.aligned.m16n8k16.row.col.f32.bf16.bf16.f32 "
                 "{%0,%1,%2,%3}, {%4,%5,%6,%7}, {%8,%9}, {%0,%1,%2,%3};"
                 : "+f"(c[0]), "+f"(c[1]), "+f"(c[2]), "+f"(c[3])
                 : "r"(a[0]), "r"(a[1]), "r"(a[2]), "r"(a[3]), "r"(b[0]), "r"(b[1]));
}

#define FBM 128
// smem layout (dynamic):
//   A:  128 rows x 264 bf16 (528B stride, conflict-free ldmatrix)  = 67584 B
//   B:  2 buffers x 16 rows x 264 bf16                             = 16896 B
//   onS: 128 floats                                                =   512 B
#define SM_A_BYTES   (128 * 264 * 2)
#define SM_B_BYTES   (2 * 16 * 264 * 2)
#define SM_TOTAL     (SM_A_BYTES + SM_B_BYTES + 512)

__global__ __launch_bounds__(512, 1)
void fused_gather_mma(const int* __restrict__ rowptr, const int* __restrict__ srcs,
                      const float* __restrict__ Xsrc, const float* __restrict__ Xres,
                      const __nv_bfloat16* __restrict__ Wb, const float* __restrict__ extra,
                      const float* __restrict__ bout, float* __restrict__ Out, int M)
{
    extern __shared__ char smem[];
    __nv_bfloat16* Asm = (__nv_bfloat16*)smem;
    __nv_bfloat16* Bsm = (__nv_bfloat16*)(smem + SM_A_BYTES);
    float* onS = (float*)(smem + SM_A_BYTES + SM_B_BYTES);

    const int tid = threadIdx.x;
    const int lane = tid & 31;
    const int warp = tid >> 5;
    const int wm0 = (warp >> 2) * 32;
    const int wn0 = (warp & 3) * 64;
    const int bm0 = blockIdx.x * FBM;

    // -------- phase 1: gather --------
#pragma unroll 1
    for (int i = 0; i < 8; i++) {
        const int rl = warp * 8 + i;
        const int r = bm0 + rl;
        float4 acc0 = make_float4(0.f, 0.f, 0.f, 0.f);
        float4 acc1 = make_float4(0.f, 0.f, 0.f, 0.f);
        int beg = 0, end = 0;
        if (r < M) { beg = rowptr[r]; end = rowptr[r + 1]; }
        int e = beg;
        // 2-way unroll for MLP
        for (; e + 1 < end; e += 2) {
            int s0 = srcs[e], s1 = srcs[e + 1];
            const float4* p0 = (const float4*)(Xsrc + (size_t)s0 * 256);
            const float4* p1 = (const float4*)(Xsrc + (size_t)s1 * 256);
            float4 u0 = p0[lane], u1 = p0[lane + 32];
            float4 w0 = p1[lane], w1 = p1[lane + 32];
            acc0.x += u0.x + w0.x; acc0.y += u0.y + w0.y;
            acc0.z += u0.z + w0.z; acc0.w += u0.w + w0.w;
            acc1.x += u1.x + w1.x; acc1.y += u1.y + w1.y;
            acc1.z += u1.z + w1.z; acc1.w += u1.w + w1.w;
        }
        if (e < end) {
            int s0 = srcs[e];
            const float4* p0 = (const float4*)(Xsrc + (size_t)s0 * 256);
            float4 u0 = p0[lane], u1 = p0[lane + 32];
            acc0.x += u0.x; acc0.y += u0.y; acc0.z += u0.z; acc0.w += u0.w;
            acc1.x += u1.x; acc1.y += u1.y; acc1.z += u1.z; acc1.w += u1.w;
        }
        const int deg = end - beg;
        const float inv = 1.0f / (float)(deg > 1 ? deg : 1);
        __nv_bfloat162 h00 = __floats2bfloat162_rn(acc0.x * inv, acc0.y * inv);
        __nv_bfloat162 h01 = __floats2bfloat162_rn(acc0.z * inv, acc0.w * inv);
        __nv_bfloat162 h10 = __floats2bfloat162_rn(acc1.x * inv, acc1.y * inv);
        __nv_bfloat162 h11 = __floats2bfloat162_rn(acc1.z * inv, acc1.w * inv);
        // cols [lane*4, lane*4+4) and [128+lane*4, ...)
        uint2 w0; w0.x = *(uint32_t*)&h00; w0.y = *(uint32_t*)&h01;
        uint2 w1; w1.x = *(uint32_t*)&h10; w1.y = *(uint32_t*)&h11;
        *(uint2*)(Asm + rl * 264 + lane * 4) = w0;
        *(uint2*)(Asm + rl * 264 + 128 + lane * 4) = w1;
        if (lane == 0) onS[rl] = (deg > 0) ? 1.0f : 0.0f;
    }

    // B tile 0 stage
    const int brow = tid >> 5;
    const int bq = tid & 31;
    const __nv_bfloat16* bptr = Wb + (size_t)brow * 256 + bq * 8;
    uint4 bReg = *(const uint4*)bptr;
    *(uint4*)(Bsm + brow * 264 + bq * 8) = bReg;
    __syncthreads();

    // -------- phase 2: MMA --------
    float acc[2][8][4];
#pragma unroll
    for (int mt = 0; mt < 2; mt++)
#pragma unroll
        for (int nt = 0; nt < 8; nt++)
#pragma unroll
            for (int j = 0; j < 4; j++) acc[mt][nt][j] = 0.f;

    const uint32_t aBase = smem_u32(Asm);
    const uint32_t bBase0 = smem_u32(Bsm);
    const uint32_t bBase1 = bBase0 + 16 * 528u;

    for (int it = 0; it < 16; it++) {
        if (it < 15)
            bReg = *(const uint4*)(bptr + (size_t)(it + 1) * 16 * 256);

        {
            const uint32_t bB = (it & 1) ? bBase1 : bBase0;
            uint32_t ra[2][4];
#pragma unroll
            for (int mt = 0; mt < 2; mt++) {
                uint32_t addr = aBase + (uint32_t)(wm0 + mt * 16 + (lane & 15)) * 528u
                              + (uint32_t)(lane >> 4) * 16u + (uint32_t)it * 32u;
                ldsm_x4(ra[mt], addr);
            }
#pragma unroll
            for (int p = 0; p < 4; p++) {
                uint32_t rb[4];
                uint32_t addr = bB + (uint32_t)(lane & 15) * 528u
                              + (uint32_t)(wn0 + p * 16 + ((lane >> 4) * 8)) * 2u;
                ldsm_x4_t(rb, addr);
#pragma unroll
                for (int mt = 0; mt < 2; mt++) {
                    mma_bf16(acc[mt][2 * p + 0], ra[mt], rb + 0);
                    mma_bf16(acc[mt][2 * p + 1], ra[mt], rb + 2);
                }
            }
        }

        if (it < 15) {
            int nb = (it + 1) & 1;
            *(uint4*)(Bsm + nb * 16 * 264 + brow * 264 + bq * 8) = bReg;
            __syncthreads();
        }
    }

    // -------- epilogue --------
    const int groupID = lane >> 2;
    const int tig = lane & 3;
#pragma unroll
    for (int nt = 0; nt < 8; nt++) {
        const int col = wn0 + nt * 8 + tig * 2;
        const float2 bo = *(const float2*)(bout + col);
        const float2 ev = *(const float2*)(extra + col);
#pragma unroll
        for (int mt = 0; mt < 2; mt++) {
            const int lrow0 = wm0 + mt * 16 + groupID;
            const int row0 = bm0 + lrow0;
            if (row0 < M) {
                float on = onS[lrow0];
                float2 xv = *(const float2*)(Xres + (size_t)row0 * 256 + col);
                float2 o;
                o.x = fmaxf(acc[mt][nt][0] + bo.x + on * ev.x + xv.x, 0.f);
                o.y = fmaxf(acc[mt][nt][1] + bo.y + on * ev.y + xv.y, 0.f);
                *(float2*)(Out + (size_t)row0 * 256 + col) = o;
            }
            const int lrow1 = lrow0 + 8;
            const int row1 = row0 + 8;
            if (row1 < M) {
                float on = onS[lrow1];
                float2 xv = *(const float2*)(Xres + (size_t)row1 * 256 + col);
                float2 o;
                o.x = fmaxf(acc[mt][nt][2] + bo.x + on * ev.x + xv.x, 0.f);
                o.y = fmaxf(acc[mt][nt][3] + bo.y + on * ev.y + xv.y, 0.f);
                *(float2*)(Out + (size_t)row1 * 256 + col) = o;
            }
        }
    }
}

// ---------------- host launch ----------------
extern "C" void kernel_launch(void* const* d_in, const int* in_sizes, int n_in,
                              void* d_out, int out_size)
{
    const float* x_user    = (const float*)d_in[0];
    const float* x_game    = (const float*)d_in[1];
    const float* Wv_user   = (const float*)d_in[6];
    const float* bv_user   = (const float*)d_in[7];
    const float* Wout_user = (const float*)d_in[8];
    const float* bout_user = (const float*)d_in[9];
    const float* Wv_game   = (const float*)d_in[14];
    const float* bv_game   = (const float*)d_in[15];
    const float* Wout_game = (const float*)d_in[16];
    const float* bout_game = (const float*)d_in[17];
    const float* Wm_played = (const float*)d_in[20];
    const float* bm_played = (const float*)d_in[21];
    const float* Wm_rev    = (const float*)d_in[24];
    const float* bm_rev    = (const float*)d_in[25];
    const int* ps = (const int*)d_in[26];
    const int* pd = (const int*)d_in[27];
    const int* rs = (const int*)d_in[28];
    const int* rd = (const int*)d_in[29];
    const int E = in_sizes[26];

    float* out = (float*)d_out;

    float *tmpA, *tmpB, *eu, *eg;
    int *rp_u, *rp_g, *cur_u, *cur_g, *srcs_u, *srcs_g, *part_u, *part_g;
    __nv_bfloat16 *Wub, *Wgb;
    cudaGetSymbolAddress((void**)&rp_u,   g_rp_u);
    cudaGetSymbolAddress((void**)&rp_g,   g_rp_g);
    cudaGetSymbolAddress((void**)&cur_u,  g_cur_u);
    cudaGetSymbolAddress((void**)&cur_g,  g_cur_g);
    cudaGetSymbolAddress((void**)&srcs_u, g_srcs_u);
    cudaGetSymbolAddress((void**)&srcs_g, g_srcs_g);
    cudaGetSymbolAddress((void**)&part_u, g_part_u);
    cudaGetSymbolAddress((void**)&part_g, g_part_g);
    cudaGetSymbolAddress((void**)&tmpA,   g_tmpA);
    cudaGetSymbolAddress((void**)&tmpB,   g_tmpB);
    cudaGetSymbolAddress((void**)&Wub,    g_Wub);
    cudaGetSymbolAddress((void**)&Wgb,    g_Wgb);
    cudaGetSymbolAddress((void**)&eu,     g_eu);
    cudaGetSymbolAddress((void**)&eg,     g_eg);

    cudaFuncSetAttribute(fused_gather_mma,
                         cudaFuncAttributeMaxDynamicSharedMemorySize, SM_TOTAL);

    // zero rowptr arrays (tiny memsets, not kernel launches)
    cudaMemsetAsync(rp_u, 0, (size_t)(N_USER + 1) * sizeof(int));
    cudaMemsetAsync(rp_g, 0, (size_t)(N_GAME + 1) * sizeof(int));

    dim3 gz(16, 16, 2), b16(16, 16);
    const int len_u = N_USER + 1, len_g = N_GAME + 1;
    const int sgx = (len_u + 1023) / 1024;   // 98, covers game too

    // kernel 0: tmpA = Wm_played@Wout_game ; tmpB = Wm_rev@Wout_user
    gemm256_pair<<<gz, b16>>>(Wm_played, Wout_game, tmpA, Wm_rev, Wout_user, tmpB);
    // kernel 1: Wgb = bf16(0.125*Wv_user@tmpA) ; Wub = bf16(0.125*Wv_game@tmpB)
    gemm256_pair_bf16<<<gz, b16>>>(Wv_user, tmpA, Wgb, Wv_game, tmpB, Wub, 0.125f);
    // kernel 2: histogram (both edge types)
    hist2<<<(E + 255) / 256, 256>>>(pd, rd, E, rp_g, rp_u);
    // kernel 3: per-block partial sums
    scanA<<<dim3(sgx, 2), 1024>>>(rp_u, len_u, part_u, rp_g, len_g, part_g);
    // kernel 4: in-place inclusive scan + cursor init
    scanC<<<dim3(sgx, 2), 1024>>>(rp_u, len_u, part_u, cur_u, rp_g, len_g, part_g, cur_g);
    // kernel 5 (profiled): bin edges into CSR
    bin_kernel<<<(E + 255) / 256, 256>>>(ps, pd, rs, rd, E, cur_g, srcs_g, cur_u, srcs_u);
    // kernel 6: fused bias chains
    vecmat_combo<<<2, 256>>>(bv_user, tmpA, bm_played, Wout_game, eg,
                             bv_game, tmpB, bm_rev, Wout_user, eu);

    // kernels 7,8: fused gather + GEMM + epilogue
    fused_gather_mma<<<(N_USER + FBM - 1) / FBM, 512, SM_TOTAL>>>(
        rp_u, srcs_u, x_game, x_user, Wub, eu, bout_user, out, N_USER);
    fused_gather_mma<<<(N_GAME + FBM - 1) / FBM, 512, SM_TOTAL>>>(
        rp_g, srcs_g, x_user, x_game, Wgb, eg, bout_game, out + (size_t)N_USER * DDIM, N_GAME);
}